// round 14
// baseline (speedup 1.0000x reference)
#include <cuda_runtime.h>
#include <math_constants.h>

#define MAX_NODES 50000
#define MAX_EDGES 800000
#define D 128
#define EPS 1e-12f

// ---------------- scratch (device globals: allocation-free) ----------------
__device__ float g_v1[D];                      // W_coef @ W_red[:128]
__device__ float g_v2[D];                      // W_coef @ W_red[128:]
__device__ float g_C;                          // folded bias constant
__device__ float g_a1[MAX_NODES];              // h[n] . v1
__device__ float g_a2[MAX_NODES];              // h[n] . v2
__device__ float g_e[MAX_EDGES];               // edge score, then exp(e - emax)
__device__ float g_emax[MAX_NODES];
__device__ float g_denom[MAX_NODES];
__device__ float g_agg[(size_t)MAX_NODES * D]; // softmax-weighted neighbor sum

// ---------------- K0: fold W_coef/W_red/biases into v1, v2, C --------------
__global__ void k0_fold(const float* __restrict__ Wcoef,
                        const float* __restrict__ bcoef,
                        const float* __restrict__ Wred,
                        const float* __restrict__ bred) {
    int d = threadIdx.x;  // 128 threads
    float v1 = 0.f, v2 = 0.f;
    #pragma unroll 8
    for (int c = 0; c < D; c++) {
        float w = Wcoef[d * D + c];
        v1 = fmaf(w, Wred[c], v1);
        v2 = fmaf(w, Wred[D + c], v2);
    }
    g_v1[d] = v1;
    g_v2[d] = v2;
    if (d == 0) {
        float C = bred[0];
        for (int c = 0; c < D; c++) C = fmaf(bcoef[c], Wred[c] + Wred[D + c], C);
        g_C = C;
    }
}

// --------- K1: per-node scalars a1,a2 + init emax/denom + zero agg ---------
__global__ void k1_node(const float* __restrict__ h, int n_nodes) {
    int warp = (blockIdx.x * blockDim.x + threadIdx.x) >> 5;
    int lane = threadIdx.x & 31;
    if (warp >= n_nodes) return;
    float4 hv = ((const float4*)h)[warp * 32 + lane];
    float4 v1 = ((const float4*)g_v1)[lane];
    float4 v2 = ((const float4*)g_v2)[lane];
    float a1 = hv.x * v1.x + hv.y * v1.y + hv.z * v1.z + hv.w * v1.w;
    float a2 = hv.x * v2.x + hv.y * v2.y + hv.z * v2.z + hv.w * v2.w;
    #pragma unroll
    for (int o = 16; o; o >>= 1) {
        a1 += __shfl_xor_sync(0xffffffffu, a1, o);
        a2 += __shfl_xor_sync(0xffffffffu, a2, o);
    }
    ((float4*)g_agg)[(size_t)warp * 32 + lane] = make_float4(0.f, 0.f, 0.f, 0.f);
    if (lane == 0) {
        g_a1[warp] = a1;
        g_a2[warp] = a2;
        g_emax[warp] = -CUDART_INF_F;
        g_denom[warp] = 0.f;
    }
}

// float atomic-max via signed/unsigned int trick (monotone bit encodings)
__device__ __forceinline__ void atomicMaxFloat(float* addr, float val) {
    if (val >= 0.f)
        atomicMax((int*)addr, __float_as_int(val));
    else
        atomicMin((unsigned int*)addr, __float_as_uint(val));
}

// ---------------- K2: edge scores + segment max ----------------------------
__global__ void k2_score(const int* __restrict__ src, const int* __restrict__ dst,
                         int n_edges) {
    int i = blockIdx.x * blockDim.x + threadIdx.x;
    if (i >= n_edges) return;
    int s = src[i], d = dst[i];
    float e = g_a1[d] + g_a2[s] + g_C;
    g_e[i] = e;
    atomicMaxFloat(&g_emax[d], e);
}

// ---------------- K3: exp(e - emax) + segment sum ---------------------------
__global__ void k3_exp(const int* __restrict__ dst, int n_edges) {
    int i = blockIdx.x * blockDim.x + threadIdx.x;
    if (i >= n_edges) return;
    int d = dst[i];
    float ex = expf(g_e[i] - g_emax[d]);
    g_e[i] = ex;
    atomicAdd(&g_denom[d], ex);
}

// ------- K4: agg[dst] += alpha * h[src], warp per edge, red.v4.f32 ----------
__global__ void k4_agg(const float* __restrict__ h,
                       const int* __restrict__ src, const int* __restrict__ dst,
                       int n_edges) {
    int e = (blockIdx.x * blockDim.x + threadIdx.x) >> 5;
    int lane = threadIdx.x & 31;
    if (e >= n_edges) return;
    int s = src[e], d = dst[e];
    float alpha = g_e[e] / (g_denom[d] + EPS);
    float4 hv = ((const float4*)h)[(size_t)s * 32 + lane];
    float x = hv.x * alpha, y = hv.y * alpha, z = hv.z * alpha, w = hv.w * alpha;
    float4* p = ((float4*)g_agg) + ((size_t)d * 32 + lane);
    asm volatile("red.global.add.v4.f32 [%0], {%1, %2, %3, %4};"
                 :: "l"(p), "f"(x), "f"(y), "f"(z), "f"(w)
                 : "memory");
}

// --------- K5: out[:, :128] = h@Wn + bn ; out[:, 128:] = agg@Wg + bg --------
// Classic 128x128 tile SGEMM, BK=8, 256 threads, 8x8 register micro-tile.
__global__ void __launch_bounds__(256, 2)
k5_gemm(const float* __restrict__ h,
        const float* __restrict__ Wn, const float* __restrict__ bn,
        const float* __restrict__ Wg, const float* __restrict__ bg,
        float* __restrict__ out, int n_nodes) {
    __shared__ float As[8][128];
    __shared__ float Bs[8][128];

    const float* A; const float* W; const float* bias; int colbase;
    if (blockIdx.z == 0) { A = h;     W = Wn; bias = bn; colbase = 0;   }
    else                 { A = g_agg; W = Wg; bias = bg; colbase = 128; }

    int r0 = blockIdx.x * 128;
    int tid = threadIdx.x;
    int aRow = tid >> 1, aHalf = tid & 1;       // A tile loader mapping
    int bRow = tid >> 5, bCol = (tid & 31) << 2; // B tile loader mapping
    int tx = tid & 15, ty = tid >> 4;
    int m0 = ty * 8, n0 = tx * 8;

    float acc[8][8];
    #pragma unroll
    for (int i = 0; i < 8; i++)
        #pragma unroll
        for (int j = 0; j < 8; j++) acc[i][j] = 0.f;

    for (int kt = 0; kt < D; kt += 8) {
        float4 fa = make_float4(0.f, 0.f, 0.f, 0.f);
        int gr = r0 + aRow;
        if (gr < n_nodes)
            fa = *(const float4*)&A[(size_t)gr * D + kt + aHalf * 4];
        As[aHalf * 4 + 0][aRow] = fa.x;
        As[aHalf * 4 + 1][aRow] = fa.y;
        As[aHalf * 4 + 2][aRow] = fa.z;
        As[aHalf * 4 + 3][aRow] = fa.w;
        *(float4*)&Bs[bRow][bCol] = *(const float4*)&W[(size_t)(kt + bRow) * D + bCol];
        __syncthreads();

        #pragma unroll
        for (int k = 0; k < 8; k++) {
            float a[8], b[8];
            *(float4*)&a[0] = *(const float4*)&As[k][m0];
            *(float4*)&a[4] = *(const float4*)&As[k][m0 + 4];
            *(float4*)&b[0] = *(const float4*)&Bs[k][n0];
            *(float4*)&b[4] = *(const float4*)&Bs[k][n0 + 4];
            #pragma unroll
            for (int i = 0; i < 8; i++)
                #pragma unroll
                for (int j = 0; j < 8; j++)
                    acc[i][j] = fmaf(a[i], b[j], acc[i][j]);
        }
        __syncthreads();
    }

    float bv[8];
    *(float4*)&bv[0] = *(const float4*)&bias[n0];
    *(float4*)&bv[4] = *(const float4*)&bias[n0 + 4];
    #pragma unroll
    for (int i = 0; i < 8; i++) {
        int gr = r0 + m0 + i;
        if (gr < n_nodes) {
            float4 o0 = make_float4(acc[i][0] + bv[0], acc[i][1] + bv[1],
                                    acc[i][2] + bv[2], acc[i][3] + bv[3]);
            float4 o1 = make_float4(acc[i][4] + bv[4], acc[i][5] + bv[5],
                                    acc[i][6] + bv[6], acc[i][7] + bv[7]);
            *(float4*)&out[(size_t)gr * 256 + colbase + n0]     = o0;
            *(float4*)&out[(size_t)gr * 256 + colbase + n0 + 4] = o1;
        }
    }
}

// ---------------- K6: row L2-normalize (warp per row) -----------------------
__global__ void k6_norm(float* __restrict__ out, int n_nodes) {
    int row = (blockIdx.x * blockDim.x + threadIdx.x) >> 5;
    int lane = threadIdx.x & 31;
    if (row >= n_nodes) return;
    float4* p = (float4*)(out + (size_t)row * 256);
    float4 a = p[lane];
    float4 b = p[lane + 32];
    float sq = a.x * a.x + a.y * a.y + a.z * a.z + a.w * a.w
             + b.x * b.x + b.y * b.y + b.z * b.z + b.w * b.w;
    #pragma unroll
    for (int o = 16; o; o >>= 1) sq += __shfl_xor_sync(0xffffffffu, sq, o);
    float r = rsqrtf(fmaxf(sq, EPS));
    a.x *= r; a.y *= r; a.z *= r; a.w *= r;
    b.x *= r; b.y *= r; b.z *= r; b.w *= r;
    p[lane] = a;
    p[lane + 32] = b;
}

// ---------------------------------------------------------------------------
extern "C" void kernel_launch(void* const* d_in, const int* in_sizes, int n_in,
                              void* d_out, int out_size) {
    const float* h      = (const float*)d_in[0];
    const int*   src    = (const int*)  d_in[1];
    const int*   dst    = (const int*)  d_in[2];
    const float* Wcoef  = (const float*)d_in[3];
    const float* bcoef  = (const float*)d_in[4];
    const float* Wred   = (const float*)d_in[5];
    const float* bred   = (const float*)d_in[6];
    const float* Wnode  = (const float*)d_in[7];
    const float* bnode  = (const float*)d_in[8];
    const float* Wneigh = (const float*)d_in[9];
    const float* bneigh = (const float*)d_in[10];
    float* out = (float*)d_out;

    int n_nodes = in_sizes[0] / D;
    int n_edges = in_sizes[1];

    k0_fold<<<1, 128>>>(Wcoef, bcoef, Wred, bred);
    k1_node<<<(n_nodes + 7) / 8, 256>>>(h, n_nodes);
    k2_score<<<(n_edges + 255) / 256, 256>>>(src, dst, n_edges);
    k3_exp<<<(n_edges + 255) / 256, 256>>>(dst, n_edges);
    k4_agg<<<(n_edges + 7) / 8, 256>>>(h, src, dst, n_edges);
    dim3 g5((n_nodes + 127) / 128, 1, 2);
    k5_gemm<<<g5, 256>>>(h, Wnode, bnode, Wneigh, bneigh, out, n_nodes);
    k6_norm<<<(n_nodes + 7) / 8, 256>>>(out, n_nodes);
}

// round 15
// speedup vs baseline: 1.0014x; 1.0014x over previous
#include <cuda_runtime.h>
#include <math_constants.h>

#define MAX_NODES 50000
#define MAX_EDGES 800000
#define D 128
#define EPS 1e-12f

// ---------------- scratch (device globals: allocation-free) ----------------
__device__ float g_v1[D];                      // W_coef @ W_red[:128]
__device__ float g_v2[D];                      // W_coef @ W_red[128:]
__device__ float g_C;                          // folded bias constant
__device__ float g_a1[MAX_NODES];              // h[n] . v1
__device__ float g_a2[MAX_NODES];              // h[n] . v2
__device__ float g_e[MAX_EDGES];               // edge score, then exp(e - emax)
__device__ float g_emax[MAX_NODES];
__device__ float g_denom[MAX_NODES];
__device__ float g_agg[(size_t)MAX_NODES * D]; // softmax-weighted neighbor sum

// ---------------- K0: fold W_coef/W_red/biases into v1, v2, C --------------
__global__ void k0_fold(const float* __restrict__ Wcoef,
                        const float* __restrict__ bcoef,
                        const float* __restrict__ Wred,
                        const float* __restrict__ bred) {
    int d = threadIdx.x;  // 128 threads
    float v1 = 0.f, v2 = 0.f;
    #pragma unroll 8
    for (int c = 0; c < D; c++) {
        float w = Wcoef[d * D + c];
        v1 = fmaf(w, Wred[c], v1);
        v2 = fmaf(w, Wred[D + c], v2);
    }
    g_v1[d] = v1;
    g_v2[d] = v2;
    if (d == 0) {
        float C = bred[0];
        for (int c = 0; c < D; c++) C = fmaf(bcoef[c], Wred[c] + Wred[D + c], C);
        g_C = C;
    }
}

// --------- K1: per-node scalars a1,a2 + init emax/denom + zero agg ---------
__global__ void k1_node(const float* __restrict__ h, int n_nodes) {
    int warp = (blockIdx.x * blockDim.x + threadIdx.x) >> 5;
    int lane = threadIdx.x & 31;
    if (warp >= n_nodes) return;
    float4 hv = ((const float4*)h)[warp * 32 + lane];
    float4 v1 = ((const float4*)g_v1)[lane];
    float4 v2 = ((const float4*)g_v2)[lane];
    float a1 = hv.x * v1.x + hv.y * v1.y + hv.z * v1.z + hv.w * v1.w;
    float a2 = hv.x * v2.x + hv.y * v2.y + hv.z * v2.z + hv.w * v2.w;
    #pragma unroll
    for (int o = 16; o; o >>= 1) {
        a1 += __shfl_xor_sync(0xffffffffu, a1, o);
        a2 += __shfl_xor_sync(0xffffffffu, a2, o);
    }
    ((float4*)g_agg)[(size_t)warp * 32 + lane] = make_float4(0.f, 0.f, 0.f, 0.f);
    if (lane == 0) {
        g_a1[warp] = a1;
        g_a2[warp] = a2;
        g_emax[warp] = -CUDART_INF_F;
        g_denom[warp] = 0.f;
    }
}

// float atomic-max via signed/unsigned int trick (monotone bit encodings)
__device__ __forceinline__ void atomicMaxFloat(float* addr, float val) {
    if (val >= 0.f)
        atomicMax((int*)addr, __float_as_int(val));
    else
        atomicMin((unsigned int*)addr, __float_as_uint(val));
}

// ---------------- K2: edge scores + segment max ----------------------------
__global__ void k2_score(const int* __restrict__ src, const int* __restrict__ dst,
                         int n_edges) {
    int i = blockIdx.x * blockDim.x + threadIdx.x;
    if (i >= n_edges) return;
    int s = src[i], d = dst[i];
    float e = g_a1[d] + g_a2[s] + g_C;
    g_e[i] = e;
    atomicMaxFloat(&g_emax[d], e);
}

// ---------------- K3: exp(e - emax) + segment sum ---------------------------
__global__ void k3_exp(const int* __restrict__ dst, int n_edges) {
    int i = blockIdx.x * blockDim.x + threadIdx.x;
    if (i >= n_edges) return;
    int d = dst[i];
    float ex = expf(g_e[i] - g_emax[d]);
    g_e[i] = ex;
    atomicAdd(&g_denom[d], ex);
}

// ------- K4: agg[dst] += alpha * h[src], warp per edge, red.v4.f32 ----------
__global__ void k4_agg(const float* __restrict__ h,
                       const int* __restrict__ src, const int* __restrict__ dst,
                       int n_edges) {
    int e = (blockIdx.x * blockDim.x + threadIdx.x) >> 5;
    int lane = threadIdx.x & 31;
    if (e >= n_edges) return;
    int s = src[e], d = dst[e];
    float alpha = g_e[e] / (g_denom[d] + EPS);
    float4 hv = ((const float4*)h)[(size_t)s * 32 + lane];
    float x = hv.x * alpha, y = hv.y * alpha, z = hv.z * alpha, w = hv.w * alpha;
    float4* p = ((float4*)g_agg) + ((size_t)d * 32 + lane);
    asm volatile("red.global.add.v4.f32 [%0], {%1, %2, %3, %4};"
                 :: "l"(p), "f"(x), "f"(y), "f"(z), "f"(w)
                 : "memory");
}

// --------- K5: out[:, :128] = h@Wn + bn ; out[:, 128:] = agg@Wg + bg --------
// Classic 128x128 tile SGEMM, BK=8, 256 threads, 8x8 register micro-tile.
__global__ void __launch_bounds__(256, 2)
k5_gemm(const float* __restrict__ h,
        const float* __restrict__ Wn, const float* __restrict__ bn,
        const float* __restrict__ Wg, const float* __restrict__ bg,
        float* __restrict__ out, int n_nodes) {
    __shared__ float As[8][128];
    __shared__ float Bs[8][128];

    const float* A; const float* W; const float* bias; int colbase;
    if (blockIdx.z == 0) { A = h;     W = Wn; bias = bn; colbase = 0;   }
    else                 { A = g_agg; W = Wg; bias = bg; colbase = 128; }

    int r0 = blockIdx.x * 128;
    int tid = threadIdx.x;
    int aRow = tid >> 1, aHalf = tid & 1;       // A tile loader mapping
    int bRow = tid >> 5, bCol = (tid & 31) << 2; // B tile loader mapping
    int tx = tid & 15, ty = tid >> 4;
    int m0 = ty * 8, n0 = tx * 8;

    float acc[8][8];
    #pragma unroll
    for (int i = 0; i < 8; i++)
        #pragma unroll
        for (int j = 0; j < 8; j++) acc[i][j] = 0.f;

    for (int kt = 0; kt < D; kt += 8) {
        float4 fa = make_float4(0.f, 0.f, 0.f, 0.f);
        int gr = r0 + aRow;
        if (gr < n_nodes)
            fa = *(const float4*)&A[(size_t)gr * D + kt + aHalf * 4];
        As[aHalf * 4 + 0][aRow] = fa.x;
        As[aHalf * 4 + 1][aRow] = fa.y;
        As[aHalf * 4 + 2][aRow] = fa.z;
        As[aHalf * 4 + 3][aRow] = fa.w;
        *(float4*)&Bs[bRow][bCol] = *(const float4*)&W[(size_t)(kt + bRow) * D + bCol];
        __syncthreads();

        #pragma unroll
        for (int k = 0; k < 8; k++) {
            float a[8], b[8];
            *(float4*)&a[0] = *(const float4*)&As[k][m0];
            *(float4*)&a[4] = *(const float4*)&As[k][m0 + 4];
            *(float4*)&b[0] = *(const float4*)&Bs[k][n0];
            *(float4*)&b[4] = *(const float4*)&Bs[k][n0 + 4];
            #pragma unroll
            for (int i = 0; i < 8; i++)
                #pragma unroll
                for (int j = 0; j < 8; j++)
                    acc[i][j] = fmaf(a[i], b[j], acc[i][j]);
        }
        __syncthreads();
    }

    float bv[8];
    *(float4*)&bv[0] = *(const float4*)&bias[n0];
    *(float4*)&bv[4] = *(const float4*)&bias[n0 + 4];
    #pragma unroll
    for (int i = 0; i < 8; i++) {
        int gr = r0 + m0 + i;
        if (gr < n_nodes) {
            float4 o0 = make_float4(acc[i][0] + bv[0], acc[i][1] + bv[1],
                                    acc[i][2] + bv[2], acc[i][3] + bv[3]);
            float4 o1 = make_float4(acc[i][4] + bv[4], acc[i][5] + bv[5],
                                    acc[i][6] + bv[6], acc[i][7] + bv[7]);
            *(float4*)&out[(size_t)gr * 256 + colbase + n0]     = o0;
            *(float4*)&out[(size_t)gr * 256 + colbase + n0 + 4] = o1;
        }
    }
}

// ---------------- K6: row L2-normalize (warp per row) -----------------------
__global__ void k6_norm(float* __restrict__ out, int n_nodes) {
    int row = (blockIdx.x * blockDim.x + threadIdx.x) >> 5;
    int lane = threadIdx.x & 31;
    if (row >= n_nodes) return;
    float4* p = (float4*)(out + (size_t)row * 256);
    float4 a = p[lane];
    float4 b = p[lane + 32];
    float sq = a.x * a.x + a.y * a.y + a.z * a.z + a.w * a.w
             + b.x * b.x + b.y * b.y + b.z * b.z + b.w * b.w;
    #pragma unroll
    for (int o = 16; o; o >>= 1) sq += __shfl_xor_sync(0xffffffffu, sq, o);
    float r = rsqrtf(fmaxf(sq, EPS));
    a.x *= r; a.y *= r; a.z *= r; a.w *= r;
    b.x *= r; b.y *= r; b.z *= r; b.w *= r;
    p[lane] = a;
    p[lane + 32] = b;
}

// ---------------------------------------------------------------------------
extern "C" void kernel_launch(void* const* d_in, const int* in_sizes, int n_in,
                              void* d_out, int out_size) {
    const float* h      = (const float*)d_in[0];
    const int*   src    = (const int*)  d_in[1];
    const int*   dst    = (const int*)  d_in[2];
    const float* Wcoef  = (const float*)d_in[3];
    const float* bcoef  = (const float*)d_in[4];
    const float* Wred   = (const float*)d_in[5];
    const float* bred   = (const float*)d_in[6];
    const float* Wnode  = (const float*)d_in[7];
    const float* bnode  = (const float*)d_in[8];
    const float* Wneigh = (const float*)d_in[9];
    const float* bneigh = (const float*)d_in[10];
    float* out = (float*)d_out;

    int n_nodes = in_sizes[0] / D;
    int n_edges = in_sizes[1];

    k0_fold<<<1, 128>>>(Wcoef, bcoef, Wred, bred);
    k1_node<<<(n_nodes + 7) / 8, 256>>>(h, n_nodes);
    k2_score<<<(n_edges + 255) / 256, 256>>>(src, dst, n_edges);
    k3_exp<<<(n_edges + 255) / 256, 256>>>(dst, n_edges);
    k4_agg<<<(n_edges + 7) / 8, 256>>>(h, src, dst, n_edges);
    dim3 g5((n_nodes + 127) / 128, 1, 2);
    k5_gemm<<<g5, 256>>>(h, Wnode, bnode, Wneigh, bneigh, out, n_nodes);
    k6_norm<<<(n_nodes + 7) / 8, 256>>>(out, n_nodes);
}